// round 1
// baseline (speedup 1.0000x reference)
#include <cuda_runtime.h>
#include <math.h>

// ---------------------------------------------------------------------------
// 3-layer LSTM (H=51) + linear(2) head, B=1024, T=2048, persistent kernel.
// 128 CTAs x 408 threads; CTA owns 8 batch rows for the whole sequence.
// Thread (j = tid>>3, b = tid&7) computes all 4 gates of hidden unit j for
// batch b; cell state c stays in registers; h exchanged via SMEM.
// All weights cached in dynamic SMEM (~224 KB), rows padded to 52 floats for
// conflict-free float4 LDS.
// ---------------------------------------------------------------------------

#define Hn    51
#define HP    52          // padded row length (multiple of 4)
#define NG    204         // 4*Hn
#define Bsz   1024
#define Tn    2048
#define NBb   8           // batch rows per CTA
#define NCTA  (Bsz / NBb) // 128
#define NT    408         // 51 * 8 threads
#define CHUNK 32          // input staging chunk (timesteps)

// SMEM layout (float offsets)
#define O_WIH0 0                  // 204*2   = 408
#define O_WHH0 408                // 204*52  = 10608
#define O_WIH1 (O_WHH0 + 10608)   // 11016
#define O_WHH1 (O_WIH1 + 10608)   // 21624
#define O_WIH2 (O_WHH1 + 10608)   // 32232
#define O_WHH2 (O_WIH2 + 10608)   // 42840
#define O_BIAS (O_WHH2 + 10608)   // 53448 : 3*204 = 612 (b_ih + b_hh combined)
#define O_WLIN (O_BIAS + 612)     // 54060 : 2*52 = 104
#define O_BLIN (O_WLIN + 104)     // 54164 : 2 (+2 pad)
#define O_H    (O_BLIN + 4)       // 54168 : 3*8*52 = 1248   (16B aligned)
#define O_XS   (O_H + 1248)       // 55416 : 8*32*2 = 512
#define SM_FLOATS (O_XS + 512)    // 55928
#define SM_BYTES  (SM_FLOATS * 4) // 223712 B  ( < 232448 opt-in limit )

__device__ __forceinline__ float sigf(float x) {
    return 1.0f / (1.0f + expf(-x));
}
__device__ __forceinline__ float tanh_f(float x) {
    float e = expf(2.0f * x);          // saturates correctly at +/-inf
    return 1.0f - 2.0f / (e + 1.0f);
}

__global__ void __launch_bounds__(NT, 1) lstm_pers(
    const float* __restrict__ xin,  const float* __restrict__ tin,
    const float* __restrict__ Wih0, const float* __restrict__ Whh0,
    const float* __restrict__ bih0, const float* __restrict__ bhh0,
    const float* __restrict__ Wih1, const float* __restrict__ Whh1,
    const float* __restrict__ bih1, const float* __restrict__ bhh1,
    const float* __restrict__ Wih2, const float* __restrict__ Whh2,
    const float* __restrict__ bih2, const float* __restrict__ bhh2,
    const float* __restrict__ Wlin, const float* __restrict__ blin,
    float* __restrict__ out)
{
    extern __shared__ float sm[];
    const int tid = threadIdx.x;
    const int b0  = blockIdx.x * NBb;

    // ---- one-time weight staging (padded rows: col 51 = 0) ----
    for (int i = tid; i < NG * 2; i += NT) sm[O_WIH0 + i] = Wih0[i];
    {
        const float* srcs[5] = {Whh0, Wih1, Whh1, Wih2, Whh2};
        const int    dsts[5] = {O_WHH0, O_WIH1, O_WHH1, O_WIH2, O_WHH2};
        for (int w = 0; w < 5; w++) {
            const float* s = srcs[w];
            float*       d = sm + dsts[w];
            for (int i = tid; i < NG * HP; i += NT) {
                int r = i / HP, k = i - r * HP;
                d[i] = (k < Hn) ? s[r * Hn + k] : 0.0f;
            }
        }
    }
    for (int i = tid; i < NG; i += NT) {
        sm[O_BIAS + i]          = bih0[i] + bhh0[i];
        sm[O_BIAS + NG + i]     = bih1[i] + bhh1[i];
        sm[O_BIAS + 2 * NG + i] = bih2[i] + bhh2[i];
    }
    for (int i = tid; i < 2 * HP; i += NT) {
        int r = i / HP, k = i - r * HP;
        sm[O_WLIN + i] = (k < Hn) ? Wlin[r * Hn + k] : 0.0f;
    }
    if (tid < 2) sm[O_BLIN + tid] = blin[tid];
    for (int i = tid; i < 3 * NBb * HP; i += NT) sm[O_H + i] = 0.0f;
    __syncthreads();

    const int b = tid & (NBb - 1);
    const int j = tid >> 3;            // 0..50 (NT = 51*8 exactly)

    float* hs0 = sm + O_H + (0 * NBb + b) * HP;
    float* hs1 = sm + O_H + (1 * NBb + b) * HP;
    float* hs2 = sm + O_H + (2 * NBb + b) * HP;

    // per-thread weight row pointers (4 gate rows per layer)
    const float4* w0r0 = (const float4*)(sm + O_WHH0 + (0 * Hn + j) * HP);
    const float4* w0r1 = (const float4*)(sm + O_WHH0 + (1 * Hn + j) * HP);
    const float4* w0r2 = (const float4*)(sm + O_WHH0 + (2 * Hn + j) * HP);
    const float4* w0r3 = (const float4*)(sm + O_WHH0 + (3 * Hn + j) * HP);

    const float4* i1r0 = (const float4*)(sm + O_WIH1 + (0 * Hn + j) * HP);
    const float4* i1r1 = (const float4*)(sm + O_WIH1 + (1 * Hn + j) * HP);
    const float4* i1r2 = (const float4*)(sm + O_WIH1 + (2 * Hn + j) * HP);
    const float4* i1r3 = (const float4*)(sm + O_WIH1 + (3 * Hn + j) * HP);
    const float4* h1r0 = (const float4*)(sm + O_WHH1 + (0 * Hn + j) * HP);
    const float4* h1r1 = (const float4*)(sm + O_WHH1 + (1 * Hn + j) * HP);
    const float4* h1r2 = (const float4*)(sm + O_WHH1 + (2 * Hn + j) * HP);
    const float4* h1r3 = (const float4*)(sm + O_WHH1 + (3 * Hn + j) * HP);

    const float4* i2r0 = (const float4*)(sm + O_WIH2 + (0 * Hn + j) * HP);
    const float4* i2r1 = (const float4*)(sm + O_WIH2 + (1 * Hn + j) * HP);
    const float4* i2r2 = (const float4*)(sm + O_WIH2 + (2 * Hn + j) * HP);
    const float4* i2r3 = (const float4*)(sm + O_WIH2 + (3 * Hn + j) * HP);
    const float4* h2r0 = (const float4*)(sm + O_WHH2 + (0 * Hn + j) * HP);
    const float4* h2r1 = (const float4*)(sm + O_WHH2 + (1 * Hn + j) * HP);
    const float4* h2r2 = (const float4*)(sm + O_WHH2 + (2 * Hn + j) * HP);
    const float4* h2r3 = (const float4*)(sm + O_WHH2 + (3 * Hn + j) * HP);

    float c0 = 0.0f, c1 = 0.0f, c2 = 0.0f;

    for (int t = 0; t < Tn; t++) {
        const int tc = t & (CHUNK - 1);
        if (tc == 0) {
            __syncthreads();
            for (int i = tid; i < NBb * CHUNK; i += NT) {
                int bb = i >> 5, cc = i & 31;        // CHUNK = 32
                size_t g = (size_t)(b0 + bb) * Tn + (size_t)t + cc;
                sm[O_XS + (i << 1) + 0] = xin[g];
                sm[O_XS + (i << 1) + 1] = tin[g];
            }
            __syncthreads();
        }

        // ---------------- layer 0 ----------------
        {
            float a0 = sm[O_BIAS + 0 * Hn + j];
            float a1 = sm[O_BIAS + 1 * Hn + j];
            float a2 = sm[O_BIAS + 2 * Hn + j];
            float a3 = sm[O_BIAS + 3 * Hn + j];
            float x0 = sm[O_XS + ((b * CHUNK + tc) << 1) + 0];
            float x1 = sm[O_XS + ((b * CHUNK + tc) << 1) + 1];
            a0 += sm[O_WIH0 + (0 * Hn + j) * 2] * x0 + sm[O_WIH0 + (0 * Hn + j) * 2 + 1] * x1;
            a1 += sm[O_WIH0 + (1 * Hn + j) * 2] * x0 + sm[O_WIH0 + (1 * Hn + j) * 2 + 1] * x1;
            a2 += sm[O_WIH0 + (2 * Hn + j) * 2] * x0 + sm[O_WIH0 + (2 * Hn + j) * 2 + 1] * x1;
            a3 += sm[O_WIH0 + (3 * Hn + j) * 2] * x0 + sm[O_WIH0 + (3 * Hn + j) * 2 + 1] * x1;
            const float4* hv = (const float4*)hs0;
            #pragma unroll
            for (int k = 0; k < HP / 4; k++) {
                float4 h4 = hv[k], q;
                q = w0r0[k]; a0 += q.x * h4.x + q.y * h4.y + q.z * h4.z + q.w * h4.w;
                q = w0r1[k]; a1 += q.x * h4.x + q.y * h4.y + q.z * h4.z + q.w * h4.w;
                q = w0r2[k]; a2 += q.x * h4.x + q.y * h4.y + q.z * h4.z + q.w * h4.w;
                q = w0r3[k]; a3 += q.x * h4.x + q.y * h4.y + q.z * h4.z + q.w * h4.w;
            }
            float ig = sigf(a0), fg = sigf(a1), gg = tanh_f(a2), og = sigf(a3);
            c0 = fg * c0 + ig * gg;
            float hn = og * tanh_f(c0);
            __syncthreads();
            hs0[j] = hn;
            __syncthreads();
        }

        // ---------------- layer 1 ----------------
        {
            float a0 = sm[O_BIAS + NG + 0 * Hn + j];
            float a1 = sm[O_BIAS + NG + 1 * Hn + j];
            float a2 = sm[O_BIAS + NG + 2 * Hn + j];
            float a3 = sm[O_BIAS + NG + 3 * Hn + j];
            const float4* xv = (const float4*)hs0;
            const float4* hv = (const float4*)hs1;
            #pragma unroll
            for (int k = 0; k < HP / 4; k++) {
                float4 x4 = xv[k], h4 = hv[k], q;
                q = i1r0[k]; a0 += q.x * x4.x + q.y * x4.y + q.z * x4.z + q.w * x4.w;
                q = h1r0[k]; a0 += q.x * h4.x + q.y * h4.y + q.z * h4.z + q.w * h4.w;
                q = i1r1[k]; a1 += q.x * x4.x + q.y * x4.y + q.z * x4.z + q.w * x4.w;
                q = h1r1[k]; a1 += q.x * h4.x + q.y * h4.y + q.z * h4.z + q.w * h4.w;
                q = i1r2[k]; a2 += q.x * x4.x + q.y * x4.y + q.z * x4.z + q.w * x4.w;
                q = h1r2[k]; a2 += q.x * h4.x + q.y * h4.y + q.z * h4.z + q.w * h4.w;
                q = i1r3[k]; a3 += q.x * x4.x + q.y * x4.y + q.z * x4.z + q.w * x4.w;
                q = h1r3[k]; a3 += q.x * h4.x + q.y * h4.y + q.z * h4.z + q.w * h4.w;
            }
            float ig = sigf(a0), fg = sigf(a1), gg = tanh_f(a2), og = sigf(a3);
            c1 = fg * c1 + ig * gg;
            float hn = og * tanh_f(c1);
            __syncthreads();
            hs1[j] = hn;
            __syncthreads();
        }

        // ---------------- layer 2 ----------------
        {
            float a0 = sm[O_BIAS + 2 * NG + 0 * Hn + j];
            float a1 = sm[O_BIAS + 2 * NG + 1 * Hn + j];
            float a2 = sm[O_BIAS + 2 * NG + 2 * Hn + j];
            float a3 = sm[O_BIAS + 2 * NG + 3 * Hn + j];
            const float4* xv = (const float4*)hs1;
            const float4* hv = (const float4*)hs2;
            #pragma unroll
            for (int k = 0; k < HP / 4; k++) {
                float4 x4 = xv[k], h4 = hv[k], q;
                q = i2r0[k]; a0 += q.x * x4.x + q.y * x4.y + q.z * x4.z + q.w * x4.w;
                q = h2r0[k]; a0 += q.x * h4.x + q.y * h4.y + q.z * h4.z + q.w * h4.w;
                q = i2r1[k]; a1 += q.x * x4.x + q.y * x4.y + q.z * x4.z + q.w * x4.w;
                q = h2r1[k]; a1 += q.x * h4.x + q.y * h4.y + q.z * h4.z + q.w * h4.w;
                q = i2r2[k]; a2 += q.x * x4.x + q.y * x4.y + q.z * x4.z + q.w * x4.w;
                q = h2r2[k]; a2 += q.x * h4.x + q.y * h4.y + q.z * h4.z + q.w * h4.w;
                q = i2r3[k]; a3 += q.x * x4.x + q.y * x4.y + q.z * x4.z + q.w * x4.w;
                q = h2r3[k]; a3 += q.x * h4.x + q.y * h4.y + q.z * h4.z + q.w * h4.w;
            }
            float ig = sigf(a0), fg = sigf(a1), gg = tanh_f(a2), og = sigf(a3);
            c2 = fg * c2 + ig * gg;
            float hn = og * tanh_f(c2);
            __syncthreads();
            hs2[j] = hn;
            __syncthreads();
        }

        // ---------------- linear head + softplus ----------------
        if (tid < 2 * NBb) {
            int bb = tid >> 1, o = tid & 1;
            const float* w  = sm + O_WLIN + o * HP;
            const float* hh = sm + O_H + (2 * NBb + bb) * HP;
            float s = sm[O_BLIN + o];
            #pragma unroll
            for (int k = 0; k < Hn; k++) s += w[k] * hh[k];
            if (o) s = (s > 30.0f) ? s : log1pf(expf(s));
            out[(((size_t)(b0 + bb)) * Tn + (size_t)t) * 2 + o] = s;
        }
        // next iteration's first __syncthreads (chunk load or layer-0 write
        // barrier) protects h[2] against overwrite before the linear reads.
    }
}

extern "C" void kernel_launch(void* const* d_in, const int* in_sizes, int n_in,
                              void* d_out, int out_size)
{
    (void)in_sizes; (void)n_in; (void)out_size;
    cudaFuncSetAttribute(lstm_pers, cudaFuncAttributeMaxDynamicSharedMemorySize,
                         SM_BYTES);
    lstm_pers<<<NCTA, NT, SM_BYTES>>>(
        (const float*)d_in[0],  (const float*)d_in[1],
        (const float*)d_in[2],  (const float*)d_in[3],
        (const float*)d_in[4],  (const float*)d_in[5],
        (const float*)d_in[6],  (const float*)d_in[7],
        (const float*)d_in[8],  (const float*)d_in[9],
        (const float*)d_in[10], (const float*)d_in[11],
        (const float*)d_in[12], (const float*)d_in[13],
        (const float*)d_in[14], (const float*)d_in[15],
        (float*)d_out);
}

// round 3
// speedup vs baseline: 1.1252x; 1.1252x over previous
#include <cuda_runtime.h>
#include <math.h>

// ---------------------------------------------------------------------------
// 3-layer LSTM (H=51) + linear(2) head, B=1024, T=2048, persistent kernel.
// 128 CTAs x 408 threads. Thread (j, gp, bp): hidden unit j, gate-pair gp
// (gp0 -> gates i,g ; gp1 -> gates f,o), batch-pair bp (batches 2bp, 2bp+1).
// Gate halves combine via shfl.xor(4); h double-buffered in SMEM -> only
// 3 __syncthreads per timestep. Weights in SMEM (padded rows of 52 floats),
// activations stored as float2 batch pairs so one LDS.128 feeds 8 FMAs.
// ---------------------------------------------------------------------------

#define Hn    51
#define HP    52
#define NG    204
#define Bsz   1024
#define Tn    2048
#define NBb   8
#define NCTA  (Bsz / NBb)
#define NT    408
#define CHUNK 32

// SMEM layout (float offsets)
#define O_WHH0 0                    // 204*52
#define O_WIH1 10608
#define O_WHH1 21216
#define O_WIH2 31824
#define O_WHH2 42432
#define O_BIAS 53040                // [3][204] combined b_ih+b_hh
#define O_WLIN 53652                // [2][52]
#define O_BLIN 53756                // 2 (+2 pad)
#define O_H2   53760                // [3][2 buf][4 bp][52] float2 = 2496 floats
#define O_XS   56256                // [8][32] float2 = 512 floats
#define SM_FLOATS 56768
#define SM_BYTES  (SM_FLOATS * 4)   // 227072 B < 232448 opt-in limit

__device__ __forceinline__ float fsig(float x) {
    return __fdividef(1.0f, 1.0f + __expf(-x));
}

// acc{x,y} += wv.{x,y,z,w} * (p0,p1) where p0 = {k:b0,b1, k+1:b0,b1}, p1 = k+2,k+3
#define DOT8(accx, accy, wv, p0, p1)                           \
    accx += (wv).x * (p0).x;  accy += (wv).x * (p0).y;         \
    accx += (wv).y * (p0).z;  accy += (wv).y * (p0).w;         \
    accx += (wv).z * (p1).x;  accy += (wv).z * (p1).y;         \
    accx += (wv).w * (p1).z;  accy += (wv).w * (p1).w;

// gate combine: gp0 holds (i,g) -> product u = sig(i)*tanh(g) shfl'd to gp1;
// gp1 holds (f,o), owns c, computes and stores h (2 batches as float2).
#define LSTM_TAIL(cx, cy, dstf2)                                              \
    do {                                                                      \
        float sAx = fsig(aAx), sAy = fsig(aAy);                               \
        float vBx = __fdividef(mB, 1.0f + __expf(-mB * aBx)) - mBm1;          \
        float vBy = __fdividef(mB, 1.0f + __expf(-mB * aBy)) - mBm1;          \
        float ux = __shfl_xor_sync(shmask, sAx * vBx, 4);                     \
        float uy = __shfl_xor_sync(shmask, sAy * vBy, 4);                     \
        if (gp) {                                                             \
            cx = sAx * cx + ux;                                               \
            cy = sAy * cy + uy;                                               \
            float thx = __fdividef(2.0f, 1.0f + __expf(-2.0f * cx)) - 1.0f;   \
            float thy = __fdividef(2.0f, 1.0f + __expf(-2.0f * cy)) - 1.0f;   \
            (dstf2)[j] = make_float2(vBx * thx, vBy * thy);                    \
        }                                                                     \
    } while (0)

__global__ void __launch_bounds__(NT, 1) lstm_pers(
    const float* __restrict__ xin,  const float* __restrict__ tin,
    const float* __restrict__ Wih0, const float* __restrict__ Whh0,
    const float* __restrict__ bih0, const float* __restrict__ bhh0,
    const float* __restrict__ Wih1, const float* __restrict__ Whh1,
    const float* __restrict__ bih1, const float* __restrict__ bhh1,
    const float* __restrict__ Wih2, const float* __restrict__ Whh2,
    const float* __restrict__ bih2, const float* __restrict__ bhh2,
    const float* __restrict__ Wlin, const float* __restrict__ blin,
    float* __restrict__ out)
{
    extern __shared__ float sm[];
    const int tid   = threadIdx.x;
    const int bbase = blockIdx.x * NBb;

    // ---- one-time staging: 5 big matrices, padded col 51 = 0 ----
    {
        const float* srcs[5] = {Whh0, Wih1, Whh1, Wih2, Whh2};
        const int    dsts[5] = {O_WHH0, O_WIH1, O_WHH1, O_WIH2, O_WHH2};
        for (int w = 0; w < 5; w++) {
            const float* s = srcs[w];
            float*       d = sm + dsts[w];
            for (int i = tid; i < NG * HP; i += NT) {
                int r = i / HP, k = i - r * HP;
                d[i] = (k < Hn) ? s[r * Hn + k] : 0.0f;
            }
        }
    }
    for (int i = tid; i < NG; i += NT) {
        sm[O_BIAS + i]          = bih0[i] + bhh0[i];
        sm[O_BIAS + NG + i]     = bih1[i] + bhh1[i];
        sm[O_BIAS + 2 * NG + i] = bih2[i] + bhh2[i];
    }
    for (int i = tid; i < 2 * HP; i += NT) {
        int r = i / HP, k = i - r * HP;
        sm[O_WLIN + i] = (k < Hn) ? Wlin[r * Hn + k] : 0.0f;
    }
    if (tid < 2) sm[O_BLIN + tid] = blin[tid];
    for (int i = tid; i < 2496; i += NT) sm[O_H2 + i] = 0.0f;   // h buffers
    __syncthreads();

    const int j  = tid >> 3;          // 0..50
    const int gp = (tid >> 2) & 1;    // 0: gates i,g   1: gates f,o
    const int bp = tid & 3;           // batch pair (2bp, 2bp+1)
    const unsigned shmask = (tid >= 384) ? 0x00FFFFFFu : 0xFFFFFFFFu;
    const float mB   = gp ? 1.0f : 2.0f;   // gp0: tanh via 2*sig(2x)-1
    const float mBm1 = mB - 1.0f;

    const int rA = (gp ? 1 : 0) * Hn + j;  // f : i
    const int rB = (gp ? 3 : 2) * Hn + j;  // o : g

    // L0 input weights (2 cols) + biases in registers
    const float wxA0 = Wih0[rA * 2], wxA1 = Wih0[rA * 2 + 1];
    const float wxB0 = Wih0[rB * 2], wxB1 = Wih0[rB * 2 + 1];
    const float bA0 = sm[O_BIAS + rA],          bB0 = sm[O_BIAS + rB];
    const float bA1 = sm[O_BIAS + NG + rA],     bB1 = sm[O_BIAS + NG + rB];
    const float bA2 = sm[O_BIAS + 2 * NG + rA], bB2 = sm[O_BIAS + 2 * NG + rB];

    const float4* whA0 = (const float4*)(sm + O_WHH0 + rA * HP);
    const float4* whB0 = (const float4*)(sm + O_WHH0 + rB * HP);
    const float4* wiA1 = (const float4*)(sm + O_WIH1 + rA * HP);
    const float4* wiB1 = (const float4*)(sm + O_WIH1 + rB * HP);
    const float4* whA1 = (const float4*)(sm + O_WHH1 + rA * HP);
    const float4* whB1 = (const float4*)(sm + O_WHH1 + rB * HP);
    const float4* wiA2 = (const float4*)(sm + O_WIH2 + rA * HP);
    const float4* wiB2 = (const float4*)(sm + O_WIH2 + rB * HP);
    const float4* whA2 = (const float4*)(sm + O_WHH2 + rA * HP);
    const float4* whB2 = (const float4*)(sm + O_WHH2 + rB * HP);

    float* H2 = sm + O_H2;   // [(l*2+buf)*4 + bp] * 104 floats
    const float2* XS2 = (const float2*)(sm + O_XS);

    float c0x = 0, c0y = 0, c1x = 0, c1y = 0, c2x = 0, c2y = 0;

    for (int t = 0; t < Tn; t++) {
        const int tc = t & (CHUNK - 1);
        if (tc == 0) {
            // stage inputs for next 32 timesteps (prev readers done: >=1
            // barrier since any L0 read of XS)
            for (int i = tid; i < NBb * CHUNK; i += NT) {
                int bb = i >> 5, cc = i & 31;
                size_t g = (size_t)(bbase + bb) * Tn + (size_t)t + cc;
                ((float2*)(sm + O_XS))[i] = make_float2(xin[g], tin[g]);
            }
            __syncthreads();
        }
        const int bc = t & 1, bo = bc ^ 1;

        float aAx, aAy, aBx, aBy;

        // ---------------- layer 0 ----------------
        {
            aAx = bA0; aAy = bA0; aBx = bB0; aBy = bB0;
            float2 in0 = XS2[(2 * bp) * CHUNK + tc];
            float2 in1 = XS2[(2 * bp + 1) * CHUNK + tc];
            aAx += wxA0 * in0.x + wxA1 * in0.y;
            aAy += wxA0 * in1.x + wxA1 * in1.y;
            aBx += wxB0 * in0.x + wxB1 * in0.y;
            aBy += wxB0 * in1.x + wxB1 * in1.y;
            const float4* ph = (const float4*)(H2 + ((0 * 2 + bo) * 4 + bp) * 104);
            #pragma unroll
            for (int k4 = 0; k4 < 13; k4++) {
                float4 wa = whA0[k4], wb = whB0[k4];
                float4 p0 = ph[2 * k4], p1 = ph[2 * k4 + 1];
                DOT8(aAx, aAy, wa, p0, p1);
                DOT8(aBx, aBy, wb, p0, p1);
            }
            LSTM_TAIL(c0x, c0y, ((float2*)(H2 + ((0 * 2 + bc) * 4 + bp) * 104)));
        }
        __syncthreads();

        // ---------------- layer 1 ----------------
        {
            aAx = bA1; aAy = bA1; aBx = bB1; aBy = bB1;
            const float4* px = (const float4*)(H2 + ((0 * 2 + bc) * 4 + bp) * 104);
            const float4* ph = (const float4*)(H2 + ((1 * 2 + bo) * 4 + bp) * 104);
            #pragma unroll
            for (int k4 = 0; k4 < 13; k4++) {
                float4 wia = wiA1[k4], wib = wiB1[k4];
                float4 wha = whA1[k4], whb = whB1[k4];
                float4 x0 = px[2 * k4], x1 = px[2 * k4 + 1];
                float4 h0 = ph[2 * k4], h1 = ph[2 * k4 + 1];
                DOT8(aAx, aAy, wia, x0, x1);
                DOT8(aBx, aBy, wib, x0, x1);
                DOT8(aAx, aAy, wha, h0, h1);
                DOT8(aBx, aBy, whb, h0, h1);
            }
            LSTM_TAIL(c1x, c1y, ((float2*)(H2 + ((1 * 2 + bc) * 4 + bp) * 104)));
        }
        __syncthreads();

        // ---------------- layer 2 ----------------
        {
            aAx = bA2; aAy = bA2; aBx = bB2; aBy = bB2;
            const float4* px = (const float4*)(H2 + ((1 * 2 + bc) * 4 + bp) * 104);
            const float4* ph = (const float4*)(H2 + ((2 * 2 + bo) * 4 + bp) * 104);
            #pragma unroll
            for (int k4 = 0; k4 < 13; k4++) {
                float4 wia = wiA2[k4], wib = wiB2[k4];
                float4 wha = whA2[k4], whb = whB2[k4];
                float4 x0 = px[2 * k4], x1 = px[2 * k4 + 1];
                float4 h0 = ph[2 * k4], h1 = ph[2 * k4 + 1];
                DOT8(aAx, aAy, wia, x0, x1);
                DOT8(aBx, aBy, wib, x0, x1);
                DOT8(aAx, aAy, wha, h0, h1);
                DOT8(aBx, aBy, whb, h0, h1);
            }
            LSTM_TAIL(c2x, c2y, ((float2*)(H2 + ((2 * 2 + bc) * 4 + bp) * 104)));
        }
        __syncthreads();

        // ---------------- linear head + softplus ----------------
        if (tid < 16) {
            int bb = tid >> 1, o = tid & 1;
            const float2* hh = (const float2*)(H2 + ((2 * 2 + bc) * 4 + (bb >> 1)) * 104);
            const float*  w  = sm + O_WLIN + o * HP;
            int sel = bb & 1;
            float s = sm[O_BLIN + o];
            #pragma unroll
            for (int k = 0; k < Hn; k++) {
                float2 hv = hh[k];
                s += w[k] * (sel ? hv.y : hv.x);
            }
            if (o) s = (s > 30.0f) ? s : log1pf(expf(s));   // accurate softplus
            out[(((size_t)(bbase + bb)) * Tn + (size_t)t) * 2 + o] = s;
        }
        // h2[bc] next overwritten at t+2's L2 (>=4 barriers away) — safe.
    }
}

extern "C" void kernel_launch(void* const* d_in, const int* in_sizes, int n_in,
                              void* d_out, int out_size)
{
    (void)in_sizes; (void)n_in; (void)out_size;
    cudaFuncSetAttribute(lstm_pers, cudaFuncAttributeMaxDynamicSharedMemorySize,
                         SM_BYTES);
    lstm_pers<<<NCTA, NT, SM_BYTES>>>(
        (const float*)d_in[0],  (const float*)d_in[1],
        (const float*)d_in[2],  (const float*)d_in[3],
        (const float*)d_in[4],  (const float*)d_in[5],
        (const float*)d_in[6],  (const float*)d_in[7],
        (const float*)d_in[8],  (const float*)d_in[9],
        (const float*)d_in[10], (const float*)d_in[11],
        (const float*)d_in[12], (const float*)d_in[13],
        (const float*)d_in[14], (const float*)d_in[15],
        (float*)d_out);
}

// round 4
// speedup vs baseline: 1.5886x; 1.4119x over previous
#include <cuda_runtime.h>
#include <math.h>

// ---------------------------------------------------------------------------
// 3-layer LSTM (H=51) + linear(2) head, B=1024, T=2048, persistent kernel.
// 128 CTAs x 204 threads. Thread (j, b4, kh): hidden unit j (all 4 gates),
// batch quad b4 (batches 4*b4..4*b4+3), k-half kh (7 float4 chunks each).
// Partial sums combined across the kh pair via shfl_xor(1). Activations in
// SMEM as float4-over-4-batches (row stride 12 floats); weights in SMEM with
// rows padded to 52 floats. One LDS.128 weight load feeds 16 FMA.
// ---------------------------------------------------------------------------

#define Hn    51
#define NG    204
#define Bsz   1024
#define Tn    2048
#define NBb   8
#define NCTA  128
#define NT    204
#define CHUNK 16
#define AST   12                 // activation row stride (floats)
#define HROWS 56                 // 51 real + zero padding to cover kh1 chunk 7
#define HBUF  (HROWS * AST)      // 672 floats per (layer,buf)
#define GOFF  (Hn * 52)          // 2652: gate-row stride in a weight matrix

// SMEM float offsets
#define O_WHH0 0
#define O_WIH1 10608
#define O_WHH1 21216
#define O_WIH2 31824
#define O_WHH2 42432
#define O_BIAS 53040             // [3][204]
#define O_WLIN 53652             // [2][52]
#define O_BLIN 53756             // 2 (+2 pad)
#define O_H    53760             // 6 * 672 = 4032
#define O_XS   (O_H + 6 * HBUF)  // 57792 : [16][16]
#define SM_FLOATS (O_XS + CHUNK * 16)   // 58048
#define SM_BYTES  (SM_FLOATS * 4)       // 232192 <= 232448

__device__ __forceinline__ float fsig(float x) {
    return __fdividef(1.0f, 1.0f + __expf(-x));
}
__device__ __forceinline__ float ftanh(float x) {
    return __fdividef(2.0f, 1.0f + __expf(-2.0f * x)) - 1.0f;
}

// acc(float4 over batches) += w.k * act_k(float4 over batches), k = 0..3
#define DOTG(acc, wv, v0, v1, v2, v3)                                  \
    (acc).x += (wv).x * (v0).x; (acc).y += (wv).x * (v0).y;            \
    (acc).z += (wv).x * (v0).z; (acc).w += (wv).x * (v0).w;            \
    (acc).x += (wv).y * (v1).x; (acc).y += (wv).y * (v1).y;            \
    (acc).z += (wv).y * (v1).z; (acc).w += (wv).y * (v1).w;            \
    (acc).x += (wv).z * (v2).x; (acc).y += (wv).z * (v2).y;            \
    (acc).z += (wv).z * (v2).z; (acc).w += (wv).z * (v2).w;            \
    (acc).x += (wv).w * (v3).x; (acc).y += (wv).w * (v3).y;            \
    (acc).z += (wv).w * (v3).z; (acc).w += (wv).w * (v3).w;

#define AXPY4(acc, s, v)                                               \
    (acc).x += (s) * (v).x; (acc).y += (s) * (v).y;                    \
    (acc).z += (s) * (v).z; (acc).w += (s) * (v).w;

// two-matrix dot: wi @ x-act + wh @ h-act, 7 chunks
__device__ __forceinline__ void dot2(const float* __restrict__ wi,
                                     const float* __restrict__ wh,
                                     const float* __restrict__ xa,
                                     const float* __restrict__ ha,
                                     float4& aI, float4& aF,
                                     float4& aG, float4& aO)
{
    #pragma unroll
    for (int c = 0; c < 7; c++) {
        const float* xp = xa + c * (4 * AST);
        float4 x0 = *(const float4*)(xp);
        float4 x1 = *(const float4*)(xp + AST);
        float4 x2 = *(const float4*)(xp + 2 * AST);
        float4 x3 = *(const float4*)(xp + 3 * AST);
        float4 w;
        w = *(const float4*)(wi + c * 4 + 0 * GOFF); DOTG(aI, w, x0, x1, x2, x3);
        w = *(const float4*)(wi + c * 4 + 1 * GOFF); DOTG(aF, w, x0, x1, x2, x3);
        w = *(const float4*)(wi + c * 4 + 2 * GOFF); DOTG(aG, w, x0, x1, x2, x3);
        w = *(const float4*)(wi + c * 4 + 3 * GOFF); DOTG(aO, w, x0, x1, x2, x3);
        const float* hp = ha + c * (4 * AST);
        float4 h0 = *(const float4*)(hp);
        float4 h1 = *(const float4*)(hp + AST);
        float4 h2 = *(const float4*)(hp + 2 * AST);
        float4 h3 = *(const float4*)(hp + 3 * AST);
        w = *(const float4*)(wh + c * 4 + 0 * GOFF); DOTG(aI, w, h0, h1, h2, h3);
        w = *(const float4*)(wh + c * 4 + 1 * GOFF); DOTG(aF, w, h0, h1, h2, h3);
        w = *(const float4*)(wh + c * 4 + 2 * GOFF); DOTG(aG, w, h0, h1, h2, h3);
        w = *(const float4*)(wh + c * 4 + 3 * GOFF); DOTG(aO, w, h0, h1, h2, h3);
    }
}

// single-matrix dot (layer 0 recurrent part)
__device__ __forceinline__ void dot1(const float* __restrict__ wh,
                                     const float* __restrict__ ha,
                                     float4& aI, float4& aF,
                                     float4& aG, float4& aO)
{
    #pragma unroll
    for (int c = 0; c < 7; c++) {
        const float* hp = ha + c * (4 * AST);
        float4 h0 = *(const float4*)(hp);
        float4 h1 = *(const float4*)(hp + AST);
        float4 h2 = *(const float4*)(hp + 2 * AST);
        float4 h3 = *(const float4*)(hp + 3 * AST);
        float4 w;
        w = *(const float4*)(wh + c * 4 + 0 * GOFF); DOTG(aI, w, h0, h1, h2, h3);
        w = *(const float4*)(wh + c * 4 + 1 * GOFF); DOTG(aF, w, h0, h1, h2, h3);
        w = *(const float4*)(wh + c * 4 + 2 * GOFF); DOTG(aG, w, h0, h1, h2, h3);
        w = *(const float4*)(wh + c * 4 + 3 * GOFF); DOTG(aO, w, h0, h1, h2, h3);
    }
}

// kh-pair reduce + lstm tail for this thread's 2 batches; store h as float2
#define RTAIL(aI, aF, aG, aO, cc0, cc1, dstoff)                               \
    do {                                                                       \
        float pi0 = kh ? (aI).z : (aI).x, pi1 = kh ? (aI).w : (aI).y;          \
        float qi0 = kh ? (aI).x : (aI).z, qi1 = kh ? (aI).y : (aI).w;          \
        float pf0 = kh ? (aF).z : (aF).x, pf1 = kh ? (aF).w : (aF).y;          \
        float qf0 = kh ? (aF).x : (aF).z, qf1 = kh ? (aF).y : (aF).w;          \
        float pg0 = kh ? (aG).z : (aG).x, pg1 = kh ? (aG).w : (aG).y;          \
        float qg0 = kh ? (aG).x : (aG).z, qg1 = kh ? (aG).y : (aG).w;          \
        float po0 = kh ? (aO).z : (aO).x, po1 = kh ? (aO).w : (aO).y;          \
        float qo0 = kh ? (aO).x : (aO).z, qo1 = kh ? (aO).y : (aO).w;          \
        pi0 += __shfl_xor_sync(mask, qi0, 1); pi1 += __shfl_xor_sync(mask, qi1, 1); \
        pf0 += __shfl_xor_sync(mask, qf0, 1); pf1 += __shfl_xor_sync(mask, qf1, 1); \
        pg0 += __shfl_xor_sync(mask, qg0, 1); pg1 += __shfl_xor_sync(mask, qg1, 1); \
        po0 += __shfl_xor_sync(mask, qo0, 1); po1 += __shfl_xor_sync(mask, qo1, 1); \
        float i0 = fsig(pi0), f0 = fsig(pf0), g0 = ftanh(pg0), o0 = fsig(po0); \
        float i1 = fsig(pi1), f1 = fsig(pf1), g1 = ftanh(pg1), o1 = fsig(po1); \
        cc0 = f0 * cc0 + i0 * g0;  cc1 = f1 * cc1 + i1 * g1;                   \
        float hh0 = o0 * ftanh(cc0), hh1 = o1 * ftanh(cc1);                    \
        *(float2*)(sm + (dstoff)) = make_float2(hh0, hh1);                     \
    } while (0)

__global__ void __launch_bounds__(NT, 1) lstm_pers(
    const float* __restrict__ xin,  const float* __restrict__ tin,
    const float* __restrict__ Wih0, const float* __restrict__ Whh0,
    const float* __restrict__ bih0, const float* __restrict__ bhh0,
    const float* __restrict__ Wih1, const float* __restrict__ Whh1,
    const float* __restrict__ bih1, const float* __restrict__ bhh1,
    const float* __restrict__ Wih2, const float* __restrict__ Whh2,
    const float* __restrict__ bih2, const float* __restrict__ bhh2,
    const float* __restrict__ Wlin, const float* __restrict__ blin,
    float* __restrict__ out)
{
    extern __shared__ float sm[];
    const int tid   = threadIdx.x;
    const int bbase = blockIdx.x * NBb;

    // ---- one-time staging: rows padded to 52 floats (col 51 = 0) ----
    {
        const float* srcs[5] = {Whh0, Wih1, Whh1, Wih2, Whh2};
        const int    dsts[5] = {O_WHH0, O_WIH1, O_WHH1, O_WIH2, O_WHH2};
        for (int w = 0; w < 5; w++) {
            const float* s = srcs[w];
            float*       d = sm + dsts[w];
            for (int i = tid; i < NG * 52; i += NT) {
                int r = i / 52, k = i - r * 52;
                d[i] = (k < Hn) ? s[r * Hn + k] : 0.0f;
            }
        }
    }
    for (int i = tid; i < NG; i += NT) {
        sm[O_BIAS + i]          = bih0[i] + bhh0[i];
        sm[O_BIAS + NG + i]     = bih1[i] + bhh1[i];
        sm[O_BIAS + 2 * NG + i] = bih2[i] + bhh2[i];
    }
    for (int i = tid; i < 2 * 52; i += NT) {
        int r = i / 52, k = i - r * 52;
        sm[O_WLIN + i] = (k < Hn) ? Wlin[r * Hn + k] : 0.0f;
    }
    if (tid < 2) sm[O_BLIN + tid] = blin[tid];
    for (int i = tid; i < 6 * HBUF; i += NT) sm[O_H + i] = 0.0f;
    __syncthreads();

    const int j  = tid >> 2;          // 0..50
    const int b4 = (tid >> 1) & 1;    // batch quad: 4*b4 .. 4*b4+3
    const int kh = tid & 1;           // k half
    const unsigned mask = (tid >= 192) ? 0x00000FFFu : 0xFFFFFFFFu;

    const int ko = kh * 28;           // weight float offset into row
    const int ka = kh * 28 * AST;     // act float offset (28 rows)

    // biases (kh=0 carries them; kh=1 contributes 0)
    const float bI0 = kh ? 0.f : sm[O_BIAS + 0 * Hn + j];
    const float bF0 = kh ? 0.f : sm[O_BIAS + 1 * Hn + j];
    const float bG0 = kh ? 0.f : sm[O_BIAS + 2 * Hn + j];
    const float bO0 = kh ? 0.f : sm[O_BIAS + 3 * Hn + j];
    const float bI1 = kh ? 0.f : sm[O_BIAS + NG + 0 * Hn + j];
    const float bF1 = kh ? 0.f : sm[O_BIAS + NG + 1 * Hn + j];
    const float bG1 = kh ? 0.f : sm[O_BIAS + NG + 2 * Hn + j];
    const float bO1 = kh ? 0.f : sm[O_BIAS + NG + 3 * Hn + j];
    const float bI2 = kh ? 0.f : sm[O_BIAS + 2 * NG + 0 * Hn + j];
    const float bF2 = kh ? 0.f : sm[O_BIAS + 2 * NG + 1 * Hn + j];
    const float bG2 = kh ? 0.f : sm[O_BIAS + 2 * NG + 2 * Hn + j];
    const float bO2 = kh ? 0.f : sm[O_BIAS + 2 * NG + 3 * Hn + j];

    // L0 input weights (2 cols, kh=0 only)
    const float wxI0 = kh ? 0.f : Wih0[(0 * Hn + j) * 2],
                wxI1 = kh ? 0.f : Wih0[(0 * Hn + j) * 2 + 1];
    const float wxF0 = kh ? 0.f : Wih0[(1 * Hn + j) * 2],
                wxF1 = kh ? 0.f : Wih0[(1 * Hn + j) * 2 + 1];
    const float wxG0 = kh ? 0.f : Wih0[(2 * Hn + j) * 2],
                wxG1 = kh ? 0.f : Wih0[(2 * Hn + j) * 2 + 1];
    const float wxO0 = kh ? 0.f : Wih0[(3 * Hn + j) * 2],
                wxO1 = kh ? 0.f : Wih0[(3 * Hn + j) * 2 + 1];

    const float* wh0 = sm + O_WHH0 + j * 52 + ko;
    const float* wi1 = sm + O_WIH1 + j * 52 + ko;
    const float* wh1 = sm + O_WHH1 + j * 52 + ko;
    const float* wi2 = sm + O_WIH2 + j * 52 + ko;
    const float* wh2 = sm + O_WHH2 + j * 52 + ko;

    const int actoff = ka + b4 * 4;
    const int hstore = j * AST + b4 * 4 + kh * 2;

    float c00 = 0, c01 = 0, c10 = 0, c11 = 0, c20 = 0, c21 = 0;

    for (int t = 0; t < Tn; t++) {
        const int tc = t & (CHUNK - 1);
        if (tc == 0) {
            for (int i = tid; i < CHUNK * 16; i += NT) {
                int tt = i >> 4, col = i & 15;
                float v;
                if (col < 8) v = xin[(size_t)(bbase + col) * Tn + t + tt];
                else         v = tin[(size_t)(bbase + col - 8) * Tn + t + tt];
                sm[O_XS + i] = v;
            }
            __syncthreads();
        }
        const int bc = t & 1, bo = bc ^ 1;

        // ---------------- layer 0 ----------------
        {
            float4 aI = make_float4(bI0, bI0, bI0, bI0);
            float4 aF = make_float4(bF0, bF0, bF0, bF0);
            float4 aG = make_float4(bG0, bG0, bG0, bG0);
            float4 aO = make_float4(bO0, bO0, bO0, bO0);
            float4 xb = *(const float4*)(sm + O_XS + tc * 16 + b4 * 4);
            float4 tb = *(const float4*)(sm + O_XS + tc * 16 + 8 + b4 * 4);
            AXPY4(aI, wxI0, xb); AXPY4(aI, wxI1, tb);
            AXPY4(aF, wxF0, xb); AXPY4(aF, wxF1, tb);
            AXPY4(aG, wxG0, xb); AXPY4(aG, wxG1, tb);
            AXPY4(aO, wxO0, xb); AXPY4(aO, wxO1, tb);
            dot1(wh0, sm + O_H + (0 + bo) * HBUF + actoff, aI, aF, aG, aO);
            RTAIL(aI, aF, aG, aO, c00, c01, O_H + (0 + bc) * HBUF + hstore);
        }
        __syncthreads();

        // ---------------- layer 1 ----------------
        {
            float4 aI = make_float4(bI1, bI1, bI1, bI1);
            float4 aF = make_float4(bF1, bF1, bF1, bF1);
            float4 aG = make_float4(bG1, bG1, bG1, bG1);
            float4 aO = make_float4(bO1, bO1, bO1, bO1);
            dot2(wi1, wh1,
                 sm + O_H + (0 + bc) * HBUF + actoff,
                 sm + O_H + (2 + bo) * HBUF + actoff, aI, aF, aG, aO);
            RTAIL(aI, aF, aG, aO, c10, c11, O_H + (2 + bc) * HBUF + hstore);
        }
        __syncthreads();

        // ---------------- layer 2 ----------------
        {
            float4 aI = make_float4(bI2, bI2, bI2, bI2);
            float4 aF = make_float4(bF2, bF2, bF2, bF2);
            float4 aG = make_float4(bG2, bG2, bG2, bG2);
            float4 aO = make_float4(bO2, bO2, bO2, bO2);
            dot2(wi2, wh2,
                 sm + O_H + (2 + bc) * HBUF + actoff,
                 sm + O_H + (4 + bo) * HBUF + actoff, aI, aF, aG, aO);
            RTAIL(aI, aF, aG, aO, c20, c21, O_H + (4 + bc) * HBUF + hstore);
        }
        __syncthreads();

        // ---------------- linear head + softplus ----------------
        if (tid < 16) {
            int bb = tid >> 1, o = tid & 1;
            const float* hh = sm + O_H + (4 + bc) * HBUF + bb;
            const float* w  = sm + O_WLIN + o * 52;
            float s = sm[O_BLIN + o];
            #pragma unroll
            for (int k = 0; k < Hn; k++) s += w[k] * hh[k * AST];
            if (o) s = (s > 30.0f) ? s : log1pf(expf(s));
            out[(((size_t)(bbase + bb)) * Tn + (size_t)t) * 2 + o] = s;
        }
        // (2,bc) next rewritten at t+2's L2, >= 3 barriers away — safe.
    }
}

extern "C" void kernel_launch(void* const* d_in, const int* in_sizes, int n_in,
                              void* d_out, int out_size)
{
    (void)in_sizes; (void)n_in; (void)out_size;
    cudaFuncSetAttribute(lstm_pers, cudaFuncAttributeMaxDynamicSharedMemorySize,
                         SM_BYTES);
    lstm_pers<<<NCTA, NT, SM_BYTES>>>(
        (const float*)d_in[0],  (const float*)d_in[1],
        (const float*)d_in[2],  (const float*)d_in[3],
        (const float*)d_in[4],  (const float*)d_in[5],
        (const float*)d_in[6],  (const float*)d_in[7],
        (const float*)d_in[8],  (const float*)d_in[9],
        (const float*)d_in[10], (const float*)d_in[11],
        (const float*)d_in[12], (const float*)d_in[13],
        (const float*)d_in[14], (const float*)d_in[15],
        (float*)d_out);
}

// round 6
// speedup vs baseline: 1.6572x; 1.0432x over previous
#include <cuda_runtime.h>
#include <math.h>

// ---------------------------------------------------------------------------
// 3-layer LSTM (H=51) + linear(2) head, B=1024, T=2048, persistent kernel.
// 128 CTAs x 204 threads. Thread (j, b4, kh): unit j (all 4 gates), batch
// quad b4, k-half kh. Packed fma.rn.f32x2 over k-pairs: weights read from
// SMEM directly as u64 pairs; activations stored [batch][k] (stride 60).
// Layer-0 recurrent weights cached in registers (constant over T).
// kh pair combined via shfl_xor(1); 3 __syncthreads per timestep.
// ---------------------------------------------------------------------------

#define Hn    51
#define NG    204
#define Tn    2048
#define NBb   8
#define NCTA  128
#define NT    204
#define CHUNK 16
#define ABST  60                 // act batch-row stride (floats)
#define HBUF  (8 * ABST)         // 480 floats per (layer,buf)
#define GOFF  (Hn * 52)          // 2652: gate-row stride in a weight matrix

// SMEM float offsets
#define O_WHH0 0
#define O_WIH1 10608
#define O_WHH1 21216
#define O_WIH2 31824
#define O_WHH2 42432
#define O_BIAS 53040             // [3][204]
#define O_WLIN 53652             // [2][52]
#define O_BLIN 53756             // 2 (+2 pad)
#define O_H    53760             // 6 * 480 = 2880
#define O_XS   (O_H + 6 * HBUF)  // 56640 : [16][16]
#define SM_FLOATS (O_XS + CHUNK * 16)   // 56896
#define SM_BYTES  (SM_FLOATS * 4)       // 227584 <= 232448

typedef unsigned long long ull;

__device__ __forceinline__ void f2(ull& a, ull w, ull v) {
    asm("fma.rn.f32x2 %0, %1, %2, %0;" : "+l"(a) : "l"(w), "l"(v));
}
__device__ __forceinline__ float hadd(ull v) {
    unsigned lo, hi;
    asm("mov.b64 {%0,%1}, %2;" : "=r"(lo), "=r"(hi) : "l"(v));
    return __uint_as_float(lo) + __uint_as_float(hi);
}
__device__ __forceinline__ float fsig(float x) {
    return __fdividef(1.0f, 1.0f + __expf(-x));
}
__device__ __forceinline__ float ftanh(float x) {
    return __fdividef(2.0f, 1.0f + __expf(-2.0f * x)) - 1.0f;
}

// acc[base+b] (u64 k-pair lanes) += w (2 k) * act_b (2 k), for 4 batches
#define FMA2BLK(base, wreg, a0, a1, a2, a3)                          \
    f2(acc[(base)+0], (wreg).x, (a0).x); f2(acc[(base)+0], (wreg).y, (a0).y); \
    f2(acc[(base)+1], (wreg).x, (a1).x); f2(acc[(base)+1], (wreg).y, (a1).y); \
    f2(acc[(base)+2], (wreg).x, (a2).x); f2(acc[(base)+2], (wreg).y, (a2).y); \
    f2(acc[(base)+3], (wreg).x, (a3).x); f2(acc[(base)+3], (wreg).y, (a3).y);

// combine kh pair for gate g -> full pre-acts r0, r1 for own 2 batches
#define CMB(g, r0, r1)                                                \
    {                                                                 \
        float oa = kh ? s[(g)*4+2] : s[(g)*4+0];                      \
        float ob = kh ? s[(g)*4+3] : s[(g)*4+1];                      \
        float xa = kh ? s[(g)*4+0] : s[(g)*4+2];                      \
        float xb = kh ? s[(g)*4+1] : s[(g)*4+3];                      \
        r0 = oa + __shfl_xor_sync(mask, xa, 1);                       \
        r1 = ob + __shfl_xor_sync(mask, xb, 1);                       \
    }

// two-matrix dot: wi @ x-act + wh @ h-act, 7 k-chunks of 4
__device__ __forceinline__ void dot2(const float* __restrict__ wi,
                                     const float* __restrict__ wh,
                                     const float* __restrict__ xa,
                                     const float* __restrict__ ha,
                                     ull* acc)
{
    #pragma unroll
    for (int c = 0; c < 7; c++) {
        ulonglong2 w0 = *(const ulonglong2*)(wi + 0 * GOFF + c * 4);
        ulonglong2 w1 = *(const ulonglong2*)(wi + 1 * GOFF + c * 4);
        ulonglong2 w2 = *(const ulonglong2*)(wi + 2 * GOFF + c * 4);
        ulonglong2 w3 = *(const ulonglong2*)(wi + 3 * GOFF + c * 4);
        ulonglong2 a0 = *(const ulonglong2*)(xa + 0 * ABST + c * 4);
        ulonglong2 a1 = *(const ulonglong2*)(xa + 1 * ABST + c * 4);
        ulonglong2 a2 = *(const ulonglong2*)(xa + 2 * ABST + c * 4);
        ulonglong2 a3 = *(const ulonglong2*)(xa + 3 * ABST + c * 4);
        FMA2BLK(0,  w0, a0, a1, a2, a3);
        FMA2BLK(4,  w1, a0, a1, a2, a3);
        FMA2BLK(8,  w2, a0, a1, a2, a3);
        FMA2BLK(12, w3, a0, a1, a2, a3);
        ulonglong2 v0 = *(const ulonglong2*)(wh + 0 * GOFF + c * 4);
        ulonglong2 v1 = *(const ulonglong2*)(wh + 1 * GOFF + c * 4);
        ulonglong2 v2 = *(const ulonglong2*)(wh + 2 * GOFF + c * 4);
        ulonglong2 v3 = *(const ulonglong2*)(wh + 3 * GOFF + c * 4);
        ulonglong2 h0 = *(const ulonglong2*)(ha + 0 * ABST + c * 4);
        ulonglong2 h1 = *(const ulonglong2*)(ha + 1 * ABST + c * 4);
        ulonglong2 h2 = *(const ulonglong2*)(ha + 2 * ABST + c * 4);
        ulonglong2 h3 = *(const ulonglong2*)(ha + 3 * ABST + c * 4);
        FMA2BLK(0,  v0, h0, h1, h2, h3);
        FMA2BLK(4,  v1, h0, h1, h2, h3);
        FMA2BLK(8,  v2, h0, h1, h2, h3);
        FMA2BLK(12, v3, h0, h1, h2, h3);
    }
}

__global__ void __launch_bounds__(NT, 1) lstm_pers(
    const float* __restrict__ xin,  const float* __restrict__ tin,
    const float* __restrict__ Wih0, const float* __restrict__ Whh0,
    const float* __restrict__ bih0, const float* __restrict__ bhh0,
    const float* __restrict__ Wih1, const float* __restrict__ Whh1,
    const float* __restrict__ bih1, const float* __restrict__ bhh1,
    const float* __restrict__ Wih2, const float* __restrict__ Whh2,
    const float* __restrict__ bih2, const float* __restrict__ bhh2,
    const float* __restrict__ Wlin, const float* __restrict__ blin,
    float* __restrict__ out)
{
    extern __shared__ float sm[];
    const int tid   = threadIdx.x;
    const int bbase = blockIdx.x * NBb;

    // ---- one-time staging: rows padded to 52 floats (col 51 = 0) ----
    {
        const float* srcs[5] = {Whh0, Wih1, Whh1, Wih2, Whh2};
        const int    dsts[5] = {O_WHH0, O_WIH1, O_WHH1, O_WIH2, O_WHH2};
        for (int w = 0; w < 5; w++) {
            const float* s = srcs[w];
            float*       d = sm + dsts[w];
            for (int i = tid; i < NG * 52; i += NT) {
                int r = i / 52, k = i - r * 52;
                d[i] = (k < Hn) ? s[r * Hn + k] : 0.0f;
            }
        }
    }
    for (int i = tid; i < NG; i += NT) {
        sm[O_BIAS + i]          = bih0[i] + bhh0[i];
        sm[O_BIAS + NG + i]     = bih1[i] + bhh1[i];
        sm[O_BIAS + 2 * NG + i] = bih2[i] + bhh2[i];
    }
    for (int i = tid; i < 2 * 52; i += NT) {
        int r = i / 52, k = i - r * 52;
        sm[O_WLIN + i] = (k < Hn) ? Wlin[r * Hn + k] : 0.0f;
    }
    if (tid < 2) sm[O_BLIN + tid] = blin[tid];
    for (int i = tid; i < 6 * HBUF; i += NT) sm[O_H + i] = 0.0f;
    __syncthreads();

    const int j  = tid >> 2;          // 0..50
    const int b4 = (tid >> 1) & 1;    // batch quad
    const int kh = tid & 1;           // k half
    const unsigned mask = (tid >= 192) ? 0x00000FFFu : 0xFFFFFFFFu;
    const int ko = kh * 28;

    // biases (added after kh combine, once per thread's own batches)
    const float bI0 = sm[O_BIAS + 0*Hn + j],          bF0 = sm[O_BIAS + 1*Hn + j];
    const float bG0 = sm[O_BIAS + 2*Hn + j],          bO0 = sm[O_BIAS + 3*Hn + j];
    const float bI1 = sm[O_BIAS + NG + 0*Hn + j],     bF1 = sm[O_BIAS + NG + 1*Hn + j];
    const float bG1 = sm[O_BIAS + NG + 2*Hn + j],     bO1 = sm[O_BIAS + NG + 3*Hn + j];
    const float bI2 = sm[O_BIAS + 2*NG + 0*Hn + j],   bF2 = sm[O_BIAS + 2*NG + 1*Hn + j];
    const float bG2 = sm[O_BIAS + 2*NG + 2*Hn + j],   bO2 = sm[O_BIAS + 2*NG + 3*Hn + j];

    // L0 input weights (2 cols)
    const float wxI0 = Wih0[(0*Hn + j)*2], wxI1 = Wih0[(0*Hn + j)*2 + 1];
    const float wxF0 = Wih0[(1*Hn + j)*2], wxF1 = Wih0[(1*Hn + j)*2 + 1];
    const float wxG0 = Wih0[(2*Hn + j)*2], wxG1 = Wih0[(2*Hn + j)*2 + 1];
    const float wxO0 = Wih0[(3*Hn + j)*2], wxO1 = Wih0[(3*Hn + j)*2 + 1];

    // layer-0 recurrent weights cached in registers (constant over T)
    ulonglong2 w0r[4][7];
    #pragma unroll
    for (int g = 0; g < 4; g++)
        #pragma unroll
        for (int c = 0; c < 7; c++)
            w0r[g][c] = *(const ulonglong2*)(sm + O_WHH0 + (g*Hn + j)*52 + ko + c*4);

    const float* wi1 = sm + O_WIH1 + j * 52 + ko;
    const float* wh1 = sm + O_WHH1 + j * 52 + ko;
    const float* wi2 = sm + O_WIH2 + j * 52 + ko;
    const float* wh2 = sm + O_WHH2 + j * 52 + ko;

    const int aoff = b4 * 4 * ABST + ko;   // act base offset within a buffer
    const int ob0  = b4 * 4 + kh * 2;      // own global batch indices
    const int ob1  = ob0 + 1;

    float c00 = 0, c01 = 0, c10 = 0, c11 = 0, c20 = 0, c21 = 0;

    for (int t = 0; t < Tn; t++) {
        const int tc = t & (CHUNK - 1);
        if (tc == 0) {
            for (int i = tid; i < CHUNK * 16; i += NT) {
                int tt = i >> 4, col = i & 15;
                float v;
                if (col < 8) v = xin[(size_t)(bbase + col) * Tn + t + tt];
                else         v = tin[(size_t)(bbase + col - 8) * Tn + t + tt];
                sm[O_XS + i] = v;
            }
            __syncthreads();
        }
        const int bc = t & 1, bo = bc ^ 1;

        // ---------------- layer 0 ----------------
        {
            ull acc[16];
            #pragma unroll
            for (int ii = 0; ii < 16; ii++) acc[ii] = 0ull;
            const float* ha = sm + O_H + (0 + bo) * HBUF + aoff;
            #pragma unroll
            for (int c = 0; c < 7; c++) {
                ulonglong2 h0 = *(const ulonglong2*)(ha + 0 * ABST + c * 4);
                ulonglong2 h1 = *(const ulonglong2*)(ha + 1 * ABST + c * 4);
                ulonglong2 h2 = *(const ulonglong2*)(ha + 2 * ABST + c * 4);
                ulonglong2 h3 = *(const ulonglong2*)(ha + 3 * ABST + c * 4);
                FMA2BLK(0,  w0r[0][c], h0, h1, h2, h3);
                FMA2BLK(4,  w0r[1][c], h0, h1, h2, h3);
                FMA2BLK(8,  w0r[2][c], h0, h1, h2, h3);
                FMA2BLK(12, w0r[3][c], h0, h1, h2, h3);
            }
            float s[16];
            #pragma unroll
            for (int ii = 0; ii < 16; ii++) s[ii] = hadd(acc[ii]);
            float pi0, pi1, pf0, pf1, pg0, pg1, po0, po1;
            CMB(0, pi0, pi1); CMB(1, pf0, pf1);
            CMB(2, pg0, pg1); CMB(3, po0, po1);
            float x0 = sm[O_XS + tc*16 + ob0],     x1 = sm[O_XS + tc*16 + ob1];
            float u0 = sm[O_XS + tc*16 + 8 + ob0], u1 = sm[O_XS + tc*16 + 8 + ob1];
            pi0 += bI0 + wxI0*x0 + wxI1*u0;  pi1 += bI0 + wxI0*x1 + wxI1*u1;
            pf0 += bF0 + wxF0*x0 + wxF1*u0;  pf1 += bF0 + wxF0*x1 + wxF1*u1;
            pg0 += bG0 + wxG0*x0 + wxG1*u0;  pg1 += bG0 + wxG0*x1 + wxG1*u1;
            po0 += bO0 + wxO0*x0 + wxO1*u0;  po1 += bO0 + wxO0*x1 + wxO1*u1;
            float ig0 = fsig(pi0), ig1 = fsig(pi1);
            float fg0 = fsig(pf0), fg1 = fsig(pf1);
            float gg0 = ftanh(pg0), gg1 = ftanh(pg1);
            float og0 = fsig(po0), og1 = fsig(po1);
            c00 = fg0*c00 + ig0*gg0;  c01 = fg1*c01 + ig1*gg1;
            float* hd = sm + O_H + (0 + bc) * HBUF;
            hd[ob0*ABST + j] = og0 * ftanh(c00);
            hd[ob1*ABST + j] = og1 * ftanh(c01);
        }
        __syncthreads();

        // ---------------- layer 1 ----------------
        {
            ull acc[16];
            #pragma unroll
            for (int ii = 0; ii < 16; ii++) acc[ii] = 0ull;
            dot2(wi1, wh1,
                 sm + O_H + (0 + bc) * HBUF + aoff,
                 sm + O_H + (2 + bo) * HBUF + aoff, acc);
            float s[16];
            #pragma unroll
            for (int ii = 0; ii < 16; ii++) s[ii] = hadd(acc[ii]);
            float pi0, pi1, pf0, pf1, pg0, pg1, po0, po1;
            CMB(0, pi0, pi1); CMB(1, pf0, pf1);
            CMB(2, pg0, pg1); CMB(3, po0, po1);
            float ig0 = fsig(pi0 + bI1), ig1 = fsig(pi1 + bI1);
            float fg0 = fsig(pf0 + bF1), fg1 = fsig(pf1 + bF1);
            float gg0 = ftanh(pg0 + bG1), gg1 = ftanh(pg1 + bG1);
            float og0 = fsig(po0 + bO1), og1 = fsig(po1 + bO1);
            c10 = fg0*c10 + ig0*gg0;  c11 = fg1*c11 + ig1*gg1;
            float* hd = sm + O_H + (2 + bc) * HBUF;
            hd[ob0*ABST + j] = og0 * ftanh(c10);
            hd[ob1*ABST + j] = og1 * ftanh(c11);
        }
        __syncthreads();

        // ---------------- layer 2 ----------------
        {
            ull acc[16];
            #pragma unroll
            for (int ii = 0; ii < 16; ii++) acc[ii] = 0ull;
            dot2(wi2, wh2,
                 sm + O_H + (2 + bc) * HBUF + aoff,
                 sm + O_H + (4 + bo) * HBUF + aoff, acc);
            float s[16];
            #pragma unroll
            for (int ii = 0; ii < 16; ii++) s[ii] = hadd(acc[ii]);
            float pi0, pi1, pf0, pf1, pg0, pg1, po0, po1;
            CMB(0, pi0, pi1); CMB(1, pf0, pf1);
            CMB(2, pg0, pg1); CMB(3, po0, po1);
            float ig0 = fsig(pi0 + bI2), ig1 = fsig(pi1 + bI2);
            float fg0 = fsig(pf0 + bF2), fg1 = fsig(pf1 + bF2);
            float gg0 = ftanh(pg0 + bG2), gg1 = ftanh(pg1 + bG2);
            float og0 = fsig(po0 + bO2), og1 = fsig(po1 + bO2);
            c20 = fg0*c20 + ig0*gg0;  c21 = fg1*c21 + ig1*gg1;
            float* hd = sm + O_H + (4 + bc) * HBUF;
            hd[ob0*ABST + j] = og0 * ftanh(c20);
            hd[ob1*ABST + j] = og1 * ftanh(c21);
        }
        __syncthreads();

        // ---------------- linear head + softplus ----------------
        if (tid < 16) {
            int bb = tid >> 1, o = tid & 1;
            const float* hh = sm + O_H + (4 + bc) * HBUF + bb * ABST;
            const float* w  = sm + O_WLIN + o * 52;
            float ssum = sm[O_BLIN + o];
            #pragma unroll
            for (int k = 0; k < Hn; k++) ssum += w[k] * hh[k];
            if (o) ssum = (ssum > 30.0f) ? ssum : log1pf(expf(ssum));
            out[(((size_t)(bbase + bb)) * Tn + (size_t)t) * 2 + o] = ssum;
        }
        // (4,bc) next rewritten at t+2's L2, >= 5 barriers away — safe.
    }
}

extern "C" void kernel_launch(void* const* d_in, const int* in_sizes, int n_in,
                              void* d_out, int out_size)
{
    (void)in_sizes; (void)n_in; (void)out_size;
    cudaFuncSetAttribute(lstm_pers, cudaFuncAttributeMaxDynamicSharedMemorySize,
                         SM_BYTES);
    lstm_pers<<<NCTA, NT, SM_BYTES>>>(
        (const float*)d_in[0],  (const float*)d_in[1],
        (const float*)d_in[2],  (const float*)d_in[3],
        (const float*)d_in[4],  (const float*)d_in[5],
        (const float*)d_in[6],  (const float*)d_in[7],
        (const float*)d_in[8],  (const float*)d_in[9],
        (const float*)d_in[10], (const float*)d_in[11],
        (const float*)d_in[12], (const float*)d_in[13],
        (const float*)d_in[14], (const float*)d_in[15],
        (float*)d_out);
}